// round 14
// baseline (speedup 1.0000x reference)
#include <cuda_runtime.h>
#include <cuda_fp16.h>
#include <mma.h>
#include <math.h>
#include <stdint.h>

using namespace nvcuda;

// Problem constants
#define BB   16
#define TD   64
#define TE   64
#define HD   512
#define G3   1536
#define VV   32000
#define LOGITS_ELEMS (BB*TD*VV)   // 32768000

// ---------------- scratch (__device__ globals, no allocation) ----------------
__device__ float g_xp   [BB*TD*G3];
__device__ float g_part [2*16*BB*G3];
__device__ float g_hnew [HD*BB];           // h_new staging: [j*16 + b]
__device__ float g_encp [BB*TE*HD];
__device__ float g_decp [BB*TD*HD];
__device__ float g_hlast[BB*HD];

// fp16 operands
__device__ __half g_Ah  [BB*TD*HD];
__device__ __half g_Bh  [(size_t)VV*HD];
__device__ __half g_ench[BB*TE*HD];
__device__ __half g_cat [BB*TD*2*HD];
__device__ __half g_Wae [HD*HD];
__device__ __half g_Wad [HD*HD];
__device__ __half g_Wdh [HD*2*HD];
__device__ __half g_xh  [BB*TD*HD];
__device__ __half g_Wih [G3*HD];

// barrier state: 32B-padded flags, epoch-based (2 barriers per step)
__device__ volatile unsigned int g_flags[96 * 8];
__device__ volatile unsigned int g_rel;

// ---------------- helpers ----------------
__device__ __forceinline__ uint32_t smem_u32(const void* p) {
    uint32_t a;
    asm("{ .reg .u64 t; cvta.to.shared.u64 t, %1; cvt.u32.u64 %0, t; }" : "=r"(a) : "l"(p));
    return a;
}
__device__ __forceinline__ void cp16(uint32_t s, const void* g) {
    asm volatile("cp.async.cg.shared.global [%0], [%1], 16;" :: "r"(s), "l"(g));
}
__device__ __forceinline__ void cvt8(const float* sp, __half* dp) {
    float4 v0 = *(const float4*)sp;
    float4 v1 = *(const float4*)(sp + 4);
    __half2* d = (__half2*)dp;
    d[0] = __floats2half2_rn(v0.x, v0.y);
    d[1] = __floats2half2_rn(v0.z, v0.w);
    d[2] = __floats2half2_rn(v1.x, v1.y);
    d[3] = __floats2half2_rn(v1.z, v1.w);
}
// fast, overflow-safe activations (MUFU-based, err ~1e-6)
__device__ __forceinline__ float fast_sigmoid(float a) {
    return __fdividef(1.f, 1.f + __expf(-a));
}
__device__ __forceinline__ float fast_tanh_acc(float a) {
    float t = __expf(-2.f * a);
    return __fdividef(2.f, 1.f + t) - 1.f;
}
// single-MUFU tanh (abs err ~6e-4) — only for attention energies
__device__ __forceinline__ float tanh_fast(float x) {
    float y;
    asm("tanh.approx.f32 %0, %1;" : "=f"(y) : "f"(x));
    return y;
}

// ---------------- merged convert A: x -> xh, W_ih -> Wih ----------------
#define NA1 (BB*TD*HD)
#define NA2 (G3*HD)
__global__ void convA(const float* __restrict__ x, const float* __restrict__ Wih)
{
    int i = (blockIdx.x * 256 + threadIdx.x) * 8;
    if (i < NA1) {
        cvt8(x + i, g_xh + i);
    } else {
        int j = i - NA1;
        if (j < NA2) cvt8(Wih + j, g_Wih + j);
    }
}

// ---------------- merged convert B: W_dense, W_attn (split), enc ----------------
#define NB1 (HD*2*HD)
#define NB2 (HD*2*HD)
#define NB3 (BB*TE*HD)
__global__ void convB(const float* __restrict__ Wdense,
                      const float* __restrict__ Wattn,
                      const float* __restrict__ enc)
{
    int i = (blockIdx.x * 256 + threadIdx.x) * 8;
    if (i < NB1) {
        cvt8(Wdense + i, g_Wdh + i);
    } else if (i < NB1 + NB2) {
        int j = i - NB1;
        int row = j >> 10, col = j & 1023;
        __half* dst = (col < HD) ? (g_Wae + row * HD + col)
                                 : (g_Wad + row * HD + (col - HD));
        cvt8(Wattn + j, dst);
    } else {
        int j = i - NB1 - NB2;
        if (j < NB3) cvt8(enc + j, g_ench + j);
    }
}

// ---------------- convert W_out ----------------
__global__ void convWout(const float* __restrict__ W_out)
{
    int i = (blockIdx.x * 256 + threadIdx.x) * 8;
    cvt8(W_out + i, g_Bh + i);
}

// ---------------- persistent GRU scan: 2 barriers/step, deduplicated gates ----------------
// 96 blocks = 6 g-chunks x 16 k-slices. Phase1: partial matvec. BarA.
// Phase2: 8192 gate-triples split disjointly 86/block -> g_hnew (+g_cat/g_hlast). BarB.
// Phase3: each block refreshes its sh slice (32 j x 16 b) from g_hnew.
__global__ void gru_scan(const float* __restrict__ W_hh,
                         const float* __restrict__ b_hh,
                         const int*   __restrict__ lengths)
{
    __shared__ float sW[32 * 256];
    __shared__ float sh[32 * 16];

    const int tid    = threadIdx.x;
    const int gchunk = blockIdx.x / 16;
    const int ks     = blockIdx.x % 16;
    const int g0     = gchunk * 256;
    const int hs0    = ks * 32;
    const int gg     = g0 + tid;

    const unsigned int start = g_rel;

    {
        const float4* wr = (const float4*)(W_hh + (size_t)gg * HD + hs0);
        #pragma unroll
        for (int q = 0; q < 8; q++) {
            float4 v = wr[q];
            sW[(q * 4 + 0) * 256 + tid] = v.x;
            sW[(q * 4 + 1) * 256 + tid] = v.y;
            sW[(q * 4 + 2) * 256 + tid] = v.z;
            sW[(q * 4 + 3) * 256 + tid] = v.w;
        }
    }
    sh[tid] = 0.f;
    sh[tid + 256] = 0.f;
    __syncthreads();

    // this block's disjoint gate-triple range: q = b*512 + j  (consecutive j within warp)
    const int q0 = blockIdx.x * 86;
    const int myq = q0 + tid;
    const bool hasq = (tid < 86) && (myq < 8192);
    const int qb = myq >> 9;          // batch
    const int qj = myq & 511;         // hidden dim

    for (int t = 0; t < TD; t++) {
        const int buf = t & 1;

        // ---- phase 1: partial matvec ----
        float acc[16];
        #pragma unroll
        for (int b = 0; b < 16; b++) acc[b] = 0.f;
        #pragma unroll
        for (int hrel = 0; hrel < 32; hrel++) {
            float w = sW[hrel * 256 + tid];
            const float4* hv = (const float4*)(sh + hrel * 16);
            float4 h0 = hv[0], h1 = hv[1], h2 = hv[2], h3 = hv[3];
            acc[0]  += w * h0.x; acc[1]  += w * h0.y; acc[2]  += w * h0.z; acc[3]  += w * h0.w;
            acc[4]  += w * h1.x; acc[5]  += w * h1.y; acc[6]  += w * h1.z; acc[7]  += w * h1.w;
            acc[8]  += w * h2.x; acc[9]  += w * h2.y; acc[10] += w * h2.z; acc[11] += w * h2.w;
            acc[12] += w * h3.x; acc[13] += w * h3.y; acc[14] += w * h3.z; acc[15] += w * h3.w;
        }
        {
            float* pbase = g_part + (size_t)(buf * 16 + ks) * (BB * G3);
            #pragma unroll
            for (int b = 0; b < 16; b++) pbase[(size_t)b * G3 + gg] = acc[b];
        }

        // ---- barrier A ----
        __syncthreads();
        unsigned int gen = start + 2u * (unsigned int)t + 1u;
        if (tid == 0) { __threadfence(); g_flags[blockIdx.x * 8] = gen; }
        if (tid < 96) {
            while ((int)(g_flags[tid * 8] - gen) < 0) { }
            __threadfence();
        }
        __syncthreads();

        // ---- phase 2: disjoint gates ----
        if (hasq) {
            const float* pb = g_part + (size_t)buf * 16 * BB * G3 + (size_t)qb * G3;
            float rs = 0.f, zs = 0.f, ns = 0.f;
            #pragma unroll
            for (int k2 = 0; k2 < 16; k2++) {
                const float* pp = pb + (size_t)k2 * (BB * G3);
                rs += __ldcg(pp + qj);
                zs += __ldcg(pp + 512 + qj);
                ns += __ldcg(pp + 1024 + qj);
            }
            rs += b_hh[qj];
            zs += b_hh[512 + qj];
            ns += b_hh[1024 + qj];
            const float* xr = g_xp + ((size_t)qb * TD + t) * G3;
            float r = fast_sigmoid(xr[qj] + rs);
            float z = fast_sigmoid(xr[512 + qj] + zs);
            float n = fast_tanh_acc(xr[1024 + qj] + r * ns);
            float hold = __ldcg(&g_hnew[qj * 16 + qb]);   // valid from prev step (t=0: init below)
            if (t == 0) hold = 0.f;
            float hnew = (1.f - z) * n + z * hold;
            bool  valid = (t < lengths[qb]);
            float hkeep = valid ? hnew : hold;
            g_hnew[qj * 16 + qb] = hkeep;
            g_cat[((size_t)qb * TD + t) * (2 * HD) + qj] = __float2half(valid ? hnew : 0.f);
            if (t == TD - 1) g_hlast[(size_t)qb * HD + qj] = hkeep;
        }

        // ---- barrier B ----
        __syncthreads();
        gen = start + 2u * (unsigned int)t + 2u;
        if (tid == 0) { __threadfence(); g_flags[blockIdx.x * 8] = gen; }
        if (tid < 96) {
            while ((int)(g_flags[tid * 8] - gen) < 0) { }
            __threadfence();
        }
        __syncthreads();

        // ---- phase 3: refresh sh slice [32 j x 16 b] ----
        #pragma unroll
        for (int i = 0; i < 2; i++) {
            int p = tid + i * 256;           // p = jrel*16 + b
            int jrel = p >> 4, b = p & 15;
            sh[jrel * 16 + b] = __ldcg(&g_hnew[(hs0 + jrel) * 16 + b]);
        }
        __syncthreads();
    }

    if (blockIdx.x == 0 && tid == 0) g_rel = start + 2u * (unsigned int)TD;
}

// ---------------- attention: tanh.approx energies, writes fp16 ctx into g_cat ----------------
__global__ void attn_kernel(const float* __restrict__ encp,
                            const float* __restrict__ decp,
                            const float* __restrict__ enc,
                            const int*   __restrict__ dlen,
                            const int*   __restrict__ elen,
                            const float* __restrict__ b_attn,
                            const float* __restrict__ v_w,
                            __half* __restrict__ cat)
{
    const int bd = blockIdx.x;
    const int b  = bd >> 6;
    const int d  = bd & 63;
    const int tid = threadIdx.x;

    __shared__ float s_dp[HD];
    __shared__ float s_vw[HD];
    __shared__ float s_en[TE];
    __shared__ float s_mx, s_ssum;

    __half* ctx_out = cat + (size_t)bd * (2 * HD) + HD;
    const int Dl = dlen[b];
    const int El = elen[b];

    if (d >= Dl) {
        for (int i = tid; i < HD; i += 256) ctx_out[i] = __float2half(0.f);
        return;
    }

    for (int i = tid; i < HD; i += 256) {
        s_dp[i] = decp[(size_t)bd * HD + i] + b_attn[i];
        s_vw[i] = v_w[i];
    }
    __syncthreads();

    const int warp = tid >> 5, lane = tid & 31;
    for (int e = warp; e < El; e += 8) {
        const float* ep = encp + ((size_t)b * TE + e) * HD;
        float sum = 0.f;
        #pragma unroll 4
        for (int h = lane; h < HD; h += 32)
            sum += tanh_fast(ep[h] + s_dp[h]) * s_vw[h];
        #pragma unroll
        for (int off = 16; off; off >>= 1)
            sum += __shfl_xor_sync(0xffffffffu, sum, off);
        if (lane == 0) s_en[e] = sum;
    }
    __syncthreads();

    if (tid < 32) {
        float mx = -1e30f;
        for (int e = lane; e < El; e += 32) mx = fmaxf(mx, s_en[e]);
        #pragma unroll
        for (int off = 16; off; off >>= 1)
            mx = fmaxf(mx, __shfl_xor_sync(0xffffffffu, mx, off));
        float ss = 0.f;
        for (int e = lane; e < El; e += 32) ss += __expf(s_en[e] - mx);
        #pragma unroll
        for (int off = 16; off; off >>= 1)
            ss += __shfl_xor_sync(0xffffffffu, ss, off);
        if (lane == 0) { s_mx = mx; s_ssum = ss; }
    }
    __syncthreads();
    if (tid < TE) s_en[tid] = (tid < El) ? __fdividef(__expf(s_en[tid] - s_mx), s_ssum) : 0.f;
    __syncthreads();

    for (int h = tid; h < HD; h += 256) {
        float a = 0.f;
        for (int e = 0; e < El; e++)
            a += s_en[e] * enc[((size_t)b * TE + e) * HD + h];
        ctx_out[h] = __float2half(a);
    }
}

// ---------------- generic fp16 wmma NT GEMM ----------------
#define HF_TANH 1
#define HF_OUTH 2
#define HLDT 72
#define HARR (64 * HLDT)
#define HSTAGE (2 * HARR)
#define HSMEM (2 * HSTAGE * 2)    // 36864 B
#define HLDC 36

__device__ __forceinline__ void hload_stage(const __half* __restrict__ A, int lda,
                                            const __half* __restrict__ B, int ldb,
                                            int row0, int n0, int c,
                                            uint32_t smbase, int s, int tid)
{
    #pragma unroll
    for (int it = 0; it < 4; it++) {
        int i = tid + it * 128;
        int r = i >> 3, c4 = i & 7;
        const void* src = A + (size_t)(row0 + r) * lda + c * 64 + c4 * 8;
        cp16(smbase + (uint32_t)(s * HSTAGE) * 2u + (uint32_t)(r * (HLDT * 2) + c4 * 16), src);
    }
    #pragma unroll
    for (int it = 0; it < 4; it++) {
        int i = tid + it * 128;
        int r = i >> 3, c4 = i & 7;
        const void* src = B + (size_t)(n0 + r) * ldb + c * 64 + c4 * 8;
        cp16(smbase + (uint32_t)(s * HSTAGE + HARR) * 2u + (uint32_t)(r * (HLDT * 2) + c4 * 16), src);
    }
    asm volatile("cp.async.commit_group;" ::: "memory");
}

__global__ void __launch_bounds__(128, 2) hgemm_nt(
    const __half* __restrict__ A, int lda,
    const __half* __restrict__ B, int ldb,
    const float* __restrict__ bias,
    void* __restrict__ Cout, int ldc,
    int K, int flags)
{
    extern __shared__ __align__(16) char dsm[];
    __half* sm = (__half*)dsm;
    const uint32_t smbase = smem_u32(dsm);

    const int tid = threadIdx.x;
    const int wid = tid >> 5, lane = tid & 31;
    const int brow0 = blockIdx.y * 64;
    const int bn0   = blockIdx.x * 64;
    const int warp_m = wid >> 1, warp_n = wid & 1;
    const int nch = K / 64;

    wmma::fragment<wmma::accumulator, 16, 16, 16, float> acc[2][2];
    #pragma unroll
    for (int i = 0; i < 2; i++)
        #pragma unroll
        for (int j = 0; j < 2; j++)
            wmma::fill_fragment(acc[i][j], 0.f);

    hload_stage(A, lda, B, ldb, brow0, bn0, 0, smbase, 0, tid);
    hload_stage(A, lda, B, ldb, brow0, bn0, 1, smbase, 1, tid);

    for (int c = 0; c < nch; c++) {
        const int s = c & 1;
        if (c < nch - 1) asm volatile("cp.async.wait_group 1;" ::: "memory");
        else             asm volatile("cp.async.wait_group 0;" ::: "memory");
        __syncthreads();

        const __half* As = sm + s * HSTAGE;
        const __half* Bs = As + HARR;

        #pragma unroll
        for (int kk = 0; kk < 64; kk += 16) {
            wmma::fragment<wmma::matrix_a, 16, 16, 16, __half, wmma::row_major> a[2];
            wmma::fragment<wmma::matrix_b, 16, 16, 16, __half, wmma::col_major> b[2];
            #pragma unroll
            for (int i = 0; i < 2; i++)
                wmma::load_matrix_sync(a[i], As + (warp_m * 32 + i * 16) * HLDT + kk, HLDT);
            #pragma unroll
            for (int j = 0; j < 2; j++)
                wmma::load_matrix_sync(b[j], Bs + (warp_n * 32 + j * 16) * HLDT + kk, HLDT);
            #pragma unroll
            for (int i = 0; i < 2; i++)
                #pragma unroll
                for (int j = 0; j < 2; j++)
                    wmma::mma_sync(acc[i][j], a[i], b[j], acc[i][j]);
        }
        __syncthreads();

        if (c + 2 < nch) hload_stage(A, lda, B, ldb, brow0, bn0, c + 2, smbase, s, tid);
    }

    __syncthreads();
    float* ws = (float*)dsm + wid * 32 * HLDC;
    #pragma unroll
    for (int i = 0; i < 2; i++)
        #pragma unroll
        for (int j = 0; j < 2; j++)
            wmma::store_matrix_sync(ws + i * 16 * HLDC + j * 16, acc[i][j],
                                    HLDC, wmma::mem_row_major);
    __syncwarp();

    const int row0 = brow0 + warp_m * 32;
    const int n0   = bn0 + warp_n * 32;
    #pragma unroll
    for (int it = 0; it < 8; it++) {
        int idx = lane + it * 32;
        int r   = idx >> 3;
        int c4  = (idx & 7) * 4;
        float4 v = *(float4*)(ws + r * HLDC + c4);
        if (bias) {
            v.x += bias[n0 + c4 + 0];
            v.y += bias[n0 + c4 + 1];
            v.z += bias[n0 + c4 + 2];
            v.w += bias[n0 + c4 + 3];
        }
        if (flags & HF_TANH) {
            v.x = fast_tanh_acc(v.x); v.y = fast_tanh_acc(v.y);
            v.z = fast_tanh_acc(v.z); v.w = fast_tanh_acc(v.w);
        }
        if (flags & HF_OUTH) {
            __half* cp = (__half*)Cout + (size_t)(row0 + r) * ldc + n0 + c4;
            *(__half2*)(cp)     = __floats2half2_rn(v.x, v.y);
            *(__half2*)(cp + 2) = __floats2half2_rn(v.z, v.w);
        } else {
            *(float4*)((float*)Cout + (size_t)(row0 + r) * ldc + n0 + c4) = v;
        }
    }
}

// ---------------- wmma logits GEMM (LBK 64) ----------------
#define LBK   64
#define LDT   72
#define ARR_ELEMS (128 * LDT)
#define STAGE_ELEMS (2 * ARR_ELEMS)
#define LDC_W 68
#define SMEM_LOGITS 73728

__device__ __forceinline__ void load_stage_logits(int tid, int mt, int nt, int c,
                                                  uint32_t smbase, int s)
{
    const __half* srcs[2] = {
        g_Ah + (size_t)mt * 128 * HD,
        g_Bh + (size_t)nt * 128 * HD
    };
    #pragma unroll
    for (int arr = 0; arr < 2; arr++) {
        #pragma unroll
        for (int it = 0; it < 8; it++) {
            int i  = tid + it * 128;
            int r  = i >> 3;
            int g  = i & 7;
            const void* src = srcs[arr] + (size_t)r * HD + c * LBK + g * 8;
            uint32_t dst = smbase + (uint32_t)(s * STAGE_ELEMS + arr * ARR_ELEMS) * 2u
                         + (uint32_t)(r * (LDT * 2) + g * 16);
            cp16(dst, src);
        }
    }
    asm volatile("cp.async.commit_group;" ::: "memory");
}

__global__ void __launch_bounds__(128, 2) logits_wmma(const float* __restrict__ b_out,
                                                      float* __restrict__ out)
{
    extern __shared__ __align__(16) char dynsmem[];
    __half* sm = (__half*)dynsmem;
    const uint32_t smbase = smem_u32(dynsmem);

    const int tid = threadIdx.x;
    const int wid = tid >> 5, lane = tid & 31;
    const int nt = blockIdx.x;
    const int mt = blockIdx.y;
    const int warp_m = wid >> 1;
    const int warp_n = wid & 1;

    wmma::fragment<wmma::accumulator, 16, 16, 16, float> acc[4][4];
    #pragma unroll
    for (int i = 0; i < 4; i++)
        #pragma unroll
        for (int j = 0; j < 4; j++)
            wmma::fill_fragment(acc[i][j], 0.f);

    load_stage_logits(tid, mt, nt, 0, smbase, 0);
    load_stage_logits(tid, mt, nt, 1, smbase, 1);

    for (int c = 0; c < 8; c++) {
        const int s = c & 1;
        if (c < 7) asm volatile("cp.async.wait_group 1;" ::: "memory");
        else       asm volatile("cp.async.wait_group 0;" ::: "memory");
        __syncthreads();

        const __half* As = sm + s * STAGE_ELEMS;
        const __half* Bs = As + ARR_ELEMS;

        #pragma unroll
        for (int kk = 0; kk < LBK; kk += 16) {
            wmma::fragment<wmma::matrix_a, 16, 16, 16, __half, wmma::row_major> a[4];
            wmma::fragment<wmma::matrix_b, 16, 16, 16, __half, wmma::col_major> b[4];
            #pragma unroll
            for (int i = 0; i < 4; i++)
                wmma::load_matrix_sync(a[i], As + (warp_m * 64 + i * 16) * LDT + kk, LDT);
            #pragma unroll
            for (int j = 0; j < 4; j++)
                wmma::load_matrix_sync(b[j], Bs + (warp_n * 64 + j * 16) * LDT + kk, LDT);
            #pragma unroll
            for (int i = 0; i < 4; i++)
                #pragma unroll
                for (int j = 0; j < 4; j++)
                    wmma::mma_sync(acc[i][j], a[i], b[j], acc[i][j]);
        }
        __syncthreads();

        if (c + 2 < 8) load_stage_logits(tid, mt, nt, c + 2, smbase, s);
    }

    __syncthreads();
    float* ws = (float*)dynsmem + wid * 64 * LDC_W;
    #pragma unroll
    for (int i = 0; i < 4; i++)
        #pragma unroll
        for (int j = 0; j < 4; j++)
            wmma::store_matrix_sync(ws + i * 16 * LDC_W + j * 16, acc[i][j],
                                    LDC_W, wmma::mem_row_major);
    __syncwarp();

    const int row0 = mt * 128 + warp_m * 64;
    const int n0   = nt * 128 + warp_n * 64;
    #pragma unroll
    for (int it = 0; it < 32; it++) {
        int idx = lane + it * 32;
        int r   = idx >> 4;
        int c4  = (idx & 15) * 4;
        float4 v = *(float4*)(ws + r * LDC_W + c4);
        v.x += b_out[n0 + c4 + 0];
        v.y += b_out[n0 + c4 + 1];
        v.z += b_out[n0 + c4 + 2];
        v.w += b_out[n0 + c4 + 3];
        *(float4*)(out + (size_t)(row0 + r) * VV + n0 + c4) = v;
    }
}

// ---------------- launch ----------------
extern "C" void kernel_launch(void* const* d_in, const int* in_sizes, int n_in,
                              void* d_out, int out_size)
{
    const float* x      = (const float*)d_in[0];
    const int*   inlen  = (const int*)  d_in[1];
    const float* enc    = (const float*)d_in[2];
    const int*   enclen = (const int*)  d_in[3];
    const float* W_ih   = (const float*)d_in[4];
    const float* W_hh   = (const float*)d_in[5];
    const float* b_ih   = (const float*)d_in[6];
    const float* b_hh   = (const float*)d_in[7];
    const float* W_attn = (const float*)d_in[8];
    const float* b_attn = (const float*)d_in[9];
    const float* v_w    = (const float*)d_in[10];
    const float* W_dense= (const float*)d_in[12];
    const float* b_dense= (const float*)d_in[13];
    const float* W_out  = (const float*)d_in[14];
    const float* b_out  = (const float*)d_in[15];

    float* out = (float*)d_out;

    float* xp    = nullptr; cudaGetSymbolAddress((void**)&xp,    g_xp);
    float* encp  = nullptr; cudaGetSymbolAddress((void**)&encp,  g_encp);
    float* decp  = nullptr; cudaGetSymbolAddress((void**)&decp,  g_decp);
    float* hlast = nullptr; cudaGetSymbolAddress((void**)&hlast, g_hlast);
    __half* Ah   = nullptr; cudaGetSymbolAddress((void**)&Ah,   g_Ah);
    __half* ench = nullptr; cudaGetSymbolAddress((void**)&ench, g_ench);
    __half* cat  = nullptr; cudaGetSymbolAddress((void**)&cat,  g_cat);
    __half* Wae  = nullptr; cudaGetSymbolAddress((void**)&Wae,  g_Wae);
    __half* Wad  = nullptr; cudaGetSymbolAddress((void**)&Wad,  g_Wad);
    __half* Wdh  = nullptr; cudaGetSymbolAddress((void**)&Wdh,  g_Wdh);
    __half* xh   = nullptr; cudaGetSymbolAddress((void**)&xh,   g_xh);
    __half* Wih  = nullptr; cudaGetSymbolAddress((void**)&Wih,  g_Wih);

    cudaFuncSetAttribute(logits_wmma, cudaFuncAttributeMaxDynamicSharedMemorySize, SMEM_LOGITS);

    // #1: merged convert (x, W_ih)
    convA<<<(NA1 + NA2) / 2048, 256>>>(x, W_ih);

    // #2: x_proj
    hgemm_nt<<<dim3(G3 / 64, (BB * TD) / 64), 128, HSMEM>>>(xh, HD, Wih, HD, b_ih, xp, G3, HD, 0);

    // #3: W_out convert (independent)
    convWout<<<((size_t)VV * HD) / 2048, 256>>>(W_out);

    // #4: GRU scan  <-- profiled launch position
    gru_scan<<<96, 256>>>(W_hh, b_hh, inlen);

    // #5: merged convert (W_dense, W_attn, enc)
    convB<<<(NB1 + NB2 + NB3) / 2048, 256>>>(W_dense, W_attn, enc);

    // #6,7: attention projections
    hgemm_nt<<<dim3(HD / 64, (BB * TE) / 64), 128, HSMEM>>>(ench, HD, Wae, HD, nullptr, encp, HD, HD, 0);
    hgemm_nt<<<dim3(HD / 64, (BB * TD) / 64), 128, HSMEM>>>(cat, 2 * HD, Wad, HD, nullptr, decp, HD, HD, 0);

    // #8: attention
    attn_kernel<<<BB * TD, 256>>>(encp, decp, enc, inlen, enclen, b_attn, v_w, cat);

    // #9: dense
    hgemm_nt<<<dim3(HD / 64, (BB * TD) / 64), 128, HSMEM>>>(cat, 2 * HD, Wdh, 2 * HD, b_dense, Ah, HD,
                                                            2 * HD, HF_TANH | HF_OUTH);

    // #10: logits
    logits_wmma<<<dim3(VV / 128, (BB * TD) / 128), 128, SMEM_LOGITS>>>(b_out, out);

    // h_last tail via async D2D copy
    cudaMemcpyAsync(out + LOGITS_ELEMS, hlast, BB * HD * sizeof(float),
                    cudaMemcpyDeviceToDevice);
}

// round 15
// speedup vs baseline: 1.2031x; 1.2031x over previous
#include <cuda_runtime.h>
#include <cuda_fp16.h>
#include <mma.h>
#include <math.h>
#include <stdint.h>

using namespace nvcuda;

// Problem constants
#define BB   16
#define TD   64
#define TE   64
#define HD   512
#define G3   1536
#define VV   32000
#define LOGITS_ELEMS (BB*TD*VV)   // 32768000

// ---------------- scratch (__device__ globals, no allocation) ----------------
__device__ float g_xp   [BB*TD*G3];
__device__ float g_part [2*16*BB*G3];
__device__ float g_encp [BB*TE*HD];
__device__ float g_decp [BB*TD*HD];
__device__ float g_hlast[BB*HD];

// fp16 operands
__device__ __half g_Ah  [BB*TD*HD];
__device__ __half g_Bh  [(size_t)VV*HD];
__device__ __half g_ench[BB*TE*HD];
__device__ __half g_cat [BB*TD*2*HD];
__device__ __half g_Wae [HD*HD];
__device__ __half g_Wad [HD*HD];
__device__ __half g_Wdh [HD*2*HD];
__device__ __half g_xh  [BB*TD*HD];
__device__ __half g_Wih [G3*HD];

// barrier state: 32B-padded flags, epoch-based (ONE barrier per step)
__device__ volatile unsigned int g_flags[96 * 8];
__device__ volatile unsigned int g_rel;

// ---------------- helpers ----------------
__device__ __forceinline__ uint32_t smem_u32(const void* p) {
    uint32_t a;
    asm("{ .reg .u64 t; cvta.to.shared.u64 t, %1; cvt.u32.u64 %0, t; }" : "=r"(a) : "l"(p));
    return a;
}
__device__ __forceinline__ void cp16(uint32_t s, const void* g) {
    asm volatile("cp.async.cg.shared.global [%0], [%1], 16;" :: "r"(s), "l"(g));
}
__device__ __forceinline__ void cvt8(const float* sp, __half* dp) {
    float4 v0 = *(const float4*)sp;
    float4 v1 = *(const float4*)(sp + 4);
    __half2* d = (__half2*)dp;
    d[0] = __floats2half2_rn(v0.x, v0.y);
    d[1] = __floats2half2_rn(v0.z, v0.w);
    d[2] = __floats2half2_rn(v1.x, v1.y);
    d[3] = __floats2half2_rn(v1.z, v1.w);
}
// fast, overflow-safe activations (MUFU-based, err ~1e-6)
__device__ __forceinline__ float fast_sigmoid(float a) {
    return __fdividef(1.f, 1.f + __expf(-a));
}
__device__ __forceinline__ float fast_tanh_acc(float a) {
    float t = __expf(-2.f * a);
    return __fdividef(2.f, 1.f + t) - 1.f;
}
// single-MUFU tanh (abs err ~6e-4) — only for attention energies
__device__ __forceinline__ float tanh_fast(float x) {
    float y;
    asm("tanh.approx.f32 %0, %1;" : "=f"(y) : "f"(x));
    return y;
}

// ---------------- merged convert A: x -> xh, W_ih -> Wih ----------------
#define NA1 (BB*TD*HD)
#define NA2 (G3*HD)
__global__ void convA(const float* __restrict__ x, const float* __restrict__ Wih)
{
    int i = (blockIdx.x * 256 + threadIdx.x) * 8;
    if (i < NA1) {
        cvt8(x + i, g_xh + i);
    } else {
        int j = i - NA1;
        if (j < NA2) cvt8(Wih + j, g_Wih + j);
    }
}

// ---------------- merged convert B: W_dense, W_attn (split), enc ----------------
#define NB1 (HD*2*HD)
#define NB2 (HD*2*HD)
#define NB3 (BB*TE*HD)
__global__ void convB(const float* __restrict__ Wdense,
                      const float* __restrict__ Wattn,
                      const float* __restrict__ enc)
{
    int i = (blockIdx.x * 256 + threadIdx.x) * 8;
    if (i < NB1) {
        cvt8(Wdense + i, g_Wdh + i);
    } else if (i < NB1 + NB2) {
        int j = i - NB1;
        int row = j >> 10, col = j & 1023;
        __half* dst = (col < HD) ? (g_Wae + row * HD + col)
                                 : (g_Wad + row * HD + (col - HD));
        cvt8(Wattn + j, dst);
    } else {
        int j = i - NB1 - NB2;
        if (j < NB3) cvt8(enc + j, g_ench + j);
    }
}

// ---------------- convert W_out ----------------
__global__ void convWout(const float* __restrict__ W_out)
{
    int i = (blockIdx.x * 256 + threadIdx.x) * 8;
    cvt8(W_out + i, g_Bh + i);
}

// ---------------- persistent GRU scan: ONE barrier/step, fast-math gates ----------------
// 96 blocks = 6 g-chunks x 16 k-slices. Phase1: partial matvec -> g_part. Barrier.
// Phase2: each block computes gates for ITS 32-j slice x all 16 b (redundant across
// gchunks but cheap with MUFU math), updating its local sh; gchunk==0 writes outputs.
__global__ void gru_scan(const float* __restrict__ W_hh,
                         const float* __restrict__ b_hh,
                         const int*   __restrict__ lengths)
{
    __shared__ float sW[32 * 256];
    __shared__ float sh[32 * 16];

    const int tid    = threadIdx.x;
    const int gchunk = blockIdx.x / 16;
    const int ks     = blockIdx.x % 16;
    const int g0     = gchunk * 256;
    const int hs0    = ks * 32;
    const int gg     = g0 + tid;

    const unsigned int start = g_rel;

    {
        const float4* wr = (const float4*)(W_hh + (size_t)gg * HD + hs0);
        #pragma unroll
        for (int q = 0; q < 8; q++) {
            float4 v = wr[q];
            sW[(q * 4 + 0) * 256 + tid] = v.x;
            sW[(q * 4 + 1) * 256 + tid] = v.y;
            sW[(q * 4 + 2) * 256 + tid] = v.z;
            sW[(q * 4 + 3) * 256 + tid] = v.w;
        }
    }
    sh[tid] = 0.f;
    sh[tid + 256] = 0.f;
    __syncthreads();

    for (int t = 0; t < TD; t++) {
        const int buf = t & 1;

        // ---- phase 1: partial matvec ----
        float acc[16];
        #pragma unroll
        for (int b = 0; b < 16; b++) acc[b] = 0.f;
        #pragma unroll
        for (int hrel = 0; hrel < 32; hrel++) {
            float w = sW[hrel * 256 + tid];
            const float4* hv = (const float4*)(sh + hrel * 16);
            float4 h0 = hv[0], h1 = hv[1], h2 = hv[2], h3 = hv[3];
            acc[0]  += w * h0.x; acc[1]  += w * h0.y; acc[2]  += w * h0.z; acc[3]  += w * h0.w;
            acc[4]  += w * h1.x; acc[5]  += w * h1.y; acc[6]  += w * h1.z; acc[7]  += w * h1.w;
            acc[8]  += w * h2.x; acc[9]  += w * h2.y; acc[10] += w * h2.z; acc[11] += w * h2.w;
            acc[12] += w * h3.x; acc[13] += w * h3.y; acc[14] += w * h3.z; acc[15] += w * h3.w;
        }
        {
            float* pbase = g_part + (size_t)(buf * 16 + ks) * (BB * G3);
            #pragma unroll
            for (int b = 0; b < 16; b++) pbase[(size_t)b * G3 + gg] = acc[b];
        }

        // ---- pure-spin all-to-all barrier (padded flags) ----
        __syncthreads();
        const unsigned int gen = start + (unsigned int)t + 1u;
        if (tid == 0) { __threadfence(); g_flags[blockIdx.x * 8] = gen; }
        if (tid < 96) {
            while ((int)(g_flags[tid * 8] - gen) < 0) { }
            __threadfence();
        }
        __syncthreads();
        // ---- end barrier ----

        // ---- phase 2: gates for this block's 32-j slice x all 16 b (fast math) ----
        #pragma unroll
        for (int i = 0; i < 2; i++) {
            int p    = tid + i * 256;
            int b    = p >> 5;
            int jrel = p & 31;
            int j    = hs0 + jrel;
            float rs = 0.f, zs = 0.f, ns = 0.f;
            const float* pb = g_part + (size_t)buf * 16 * BB * G3 + (size_t)b * G3;
            #pragma unroll
            for (int k2 = 0; k2 < 16; k2++) {
                const float* pp = pb + (size_t)k2 * (BB * G3);
                rs += __ldcg(pp + j);
                zs += __ldcg(pp + 512 + j);
                ns += __ldcg(pp + 1024 + j);
            }
            rs += b_hh[j];
            zs += b_hh[512 + j];
            ns += b_hh[1024 + j];
            const float* xr = g_xp + ((size_t)b * TD + t) * G3;
            float r = fast_sigmoid(xr[j] + rs);
            float z = fast_sigmoid(xr[512 + j] + zs);
            float n = fast_tanh_acc(xr[1024 + j] + r * ns);
            float hold = sh[jrel * 16 + b];
            float hnew = (1.f - z) * n + z * hold;
            bool  valid = (t < lengths[b]);
            float hkeep = valid ? hnew : hold;
            sh[jrel * 16 + b] = hkeep;
            if (gchunk == 0) {
                g_cat[((size_t)b * TD + t) * (2 * HD) + j] = __float2half(valid ? hnew : 0.f);
                if (t == TD - 1) g_hlast[(size_t)b * HD + j] = hkeep;
            }
        }
        __syncthreads();
    }

    if (blockIdx.x == 0 && tid == 0) g_rel = start + (unsigned int)TD;
}

// ---------------- attention: tanh.approx energies, writes fp16 ctx into g_cat ----------------
__global__ void attn_kernel(const float* __restrict__ encp,
                            const float* __restrict__ decp,
                            const float* __restrict__ enc,
                            const int*   __restrict__ dlen,
                            const int*   __restrict__ elen,
                            const float* __restrict__ b_attn,
                            const float* __restrict__ v_w,
                            __half* __restrict__ cat)
{
    const int bd = blockIdx.x;
    const int b  = bd >> 6;
    const int d  = bd & 63;
    const int tid = threadIdx.x;

    __shared__ float s_dp[HD];
    __shared__ float s_vw[HD];
    __shared__ float s_en[TE];
    __shared__ float s_mx, s_ssum;

    __half* ctx_out = cat + (size_t)bd * (2 * HD) + HD;
    const int Dl = dlen[b];
    const int El = elen[b];

    if (d >= Dl) {
        for (int i = tid; i < HD; i += 256) ctx_out[i] = __float2half(0.f);
        return;
    }

    for (int i = tid; i < HD; i += 256) {
        s_dp[i] = decp[(size_t)bd * HD + i] + b_attn[i];
        s_vw[i] = v_w[i];
    }
    __syncthreads();

    const int warp = tid >> 5, lane = tid & 31;
    for (int e = warp; e < El; e += 8) {
        const float* ep = encp + ((size_t)b * TE + e) * HD;
        float sum = 0.f;
        #pragma unroll 4
        for (int h = lane; h < HD; h += 32)
            sum += tanh_fast(ep[h] + s_dp[h]) * s_vw[h];
        #pragma unroll
        for (int off = 16; off; off >>= 1)
            sum += __shfl_xor_sync(0xffffffffu, sum, off);
        if (lane == 0) s_en[e] = sum;
    }
    __syncthreads();

    if (tid < 32) {
        float mx = -1e30f;
        for (int e = lane; e < El; e += 32) mx = fmaxf(mx, s_en[e]);
        #pragma unroll
        for (int off = 16; off; off >>= 1)
            mx = fmaxf(mx, __shfl_xor_sync(0xffffffffu, mx, off));
        float ss = 0.f;
        for (int e = lane; e < El; e += 32) ss += __expf(s_en[e] - mx);
        #pragma unroll
        for (int off = 16; off; off >>= 1)
            ss += __shfl_xor_sync(0xffffffffu, ss, off);
        if (lane == 0) { s_mx = mx; s_ssum = ss; }
    }
    __syncthreads();
    if (tid < TE) s_en[tid] = (tid < El) ? __fdividef(__expf(s_en[tid] - s_mx), s_ssum) : 0.f;
    __syncthreads();

    for (int h = tid; h < HD; h += 256) {
        float a = 0.f;
        for (int e = 0; e < El; e++)
            a += s_en[e] * enc[((size_t)b * TE + e) * HD + h];
        ctx_out[h] = __float2half(a);
    }
}

// ---------------- generic fp16 wmma NT GEMM ----------------
#define HF_TANH 1
#define HF_OUTH 2
#define HLDT 72
#define HARR (64 * HLDT)
#define HSTAGE (2 * HARR)
#define HSMEM (2 * HSTAGE * 2)    // 36864 B
#define HLDC 36

__device__ __forceinline__ void hload_stage(const __half* __restrict__ A, int lda,
                                            const __half* __restrict__ B, int ldb,
                                            int row0, int n0, int c,
                                            uint32_t smbase, int s, int tid)
{
    #pragma unroll
    for (int it = 0; it < 4; it++) {
        int i = tid + it * 128;
        int r = i >> 3, c4 = i & 7;
        const void* src = A + (size_t)(row0 + r) * lda + c * 64 + c4 * 8;
        cp16(smbase + (uint32_t)(s * HSTAGE) * 2u + (uint32_t)(r * (HLDT * 2) + c4 * 16), src);
    }
    #pragma unroll
    for (int it = 0; it < 4; it++) {
        int i = tid + it * 128;
        int r = i >> 3, c4 = i & 7;
        const void* src = B + (size_t)(n0 + r) * ldb + c * 64 + c4 * 8;
        cp16(smbase + (uint32_t)(s * HSTAGE + HARR) * 2u + (uint32_t)(r * (HLDT * 2) + c4 * 16), src);
    }
    asm volatile("cp.async.commit_group;" ::: "memory");
}

__global__ void __launch_bounds__(128, 2) hgemm_nt(
    const __half* __restrict__ A, int lda,
    const __half* __restrict__ B, int ldb,
    const float* __restrict__ bias,
    void* __restrict__ Cout, int ldc,
    int K, int flags)
{
    extern __shared__ __align__(16) char dsm[];
    __half* sm = (__half*)dsm;
    const uint32_t smbase = smem_u32(dsm);

    const int tid = threadIdx.x;
    const int wid = tid >> 5, lane = tid & 31;
    const int brow0 = blockIdx.y * 64;
    const int bn0   = blockIdx.x * 64;
    const int warp_m = wid >> 1, warp_n = wid & 1;
    const int nch = K / 64;

    wmma::fragment<wmma::accumulator, 16, 16, 16, float> acc[2][2];
    #pragma unroll
    for (int i = 0; i < 2; i++)
        #pragma unroll
        for (int j = 0; j < 2; j++)
            wmma::fill_fragment(acc[i][j], 0.f);

    hload_stage(A, lda, B, ldb, brow0, bn0, 0, smbase, 0, tid);
    hload_stage(A, lda, B, ldb, brow0, bn0, 1, smbase, 1, tid);

    for (int c = 0; c < nch; c++) {
        const int s = c & 1;
        if (c < nch - 1) asm volatile("cp.async.wait_group 1;" ::: "memory");
        else             asm volatile("cp.async.wait_group 0;" ::: "memory");
        __syncthreads();

        const __half* As = sm + s * HSTAGE;
        const __half* Bs = As + HARR;

        #pragma unroll
        for (int kk = 0; kk < 64; kk += 16) {
            wmma::fragment<wmma::matrix_a, 16, 16, 16, __half, wmma::row_major> a[2];
            wmma::fragment<wmma::matrix_b, 16, 16, 16, __half, wmma::col_major> b[2];
            #pragma unroll
            for (int i = 0; i < 2; i++)
                wmma::load_matrix_sync(a[i], As + (warp_m * 32 + i * 16) * HLDT + kk, HLDT);
            #pragma unroll
            for (int j = 0; j < 2; j++)
                wmma::load_matrix_sync(b[j], Bs + (warp_n * 32 + j * 16) * HLDT + kk, HLDT);
            #pragma unroll
            for (int i = 0; i < 2; i++)
                #pragma unroll
                for (int j = 0; j < 2; j++)
                    wmma::mma_sync(acc[i][j], a[i], b[j], acc[i][j]);
        }
        __syncthreads();

        if (c + 2 < nch) hload_stage(A, lda, B, ldb, brow0, bn0, c + 2, smbase, s, tid);
    }

    __syncthreads();
    float* ws = (float*)dsm + wid * 32 * HLDC;
    #pragma unroll
    for (int i = 0; i < 2; i++)
        #pragma unroll
        for (int j = 0; j < 2; j++)
            wmma::store_matrix_sync(ws + i * 16 * HLDC + j * 16, acc[i][j],
                                    HLDC, wmma::mem_row_major);
    __syncwarp();

    const int row0 = brow0 + warp_m * 32;
    const int n0   = bn0 + warp_n * 32;
    #pragma unroll
    for (int it = 0; it < 8; it++) {
        int idx = lane + it * 32;
        int r   = idx >> 3;
        int c4  = (idx & 7) * 4;
        float4 v = *(float4*)(ws + r * HLDC + c4);
        if (bias) {
            v.x += bias[n0 + c4 + 0];
            v.y += bias[n0 + c4 + 1];
            v.z += bias[n0 + c4 + 2];
            v.w += bias[n0 + c4 + 3];
        }
        if (flags & HF_TANH) {
            v.x = fast_tanh_acc(v.x); v.y = fast_tanh_acc(v.y);
            v.z = fast_tanh_acc(v.z); v.w = fast_tanh_acc(v.w);
        }
        if (flags & HF_OUTH) {
            __half* cp = (__half*)Cout + (size_t)(row0 + r) * ldc + n0 + c4;
            *(__half2*)(cp)     = __floats2half2_rn(v.x, v.y);
            *(__half2*)(cp + 2) = __floats2half2_rn(v.z, v.w);
        } else {
            *(float4*)((float*)Cout + (size_t)(row0 + r) * ldc + n0 + c4) = v;
        }
    }
}

// ---------------- wmma logits GEMM (LBK 64) ----------------
#define LBK   64
#define LDT   72
#define ARR_ELEMS (128 * LDT)
#define STAGE_ELEMS (2 * ARR_ELEMS)
#define LDC_W 68
#define SMEM_LOGITS 73728

__device__ __forceinline__ void load_stage_logits(int tid, int mt, int nt, int c,
                                                  uint32_t smbase, int s)
{
    const __half* srcs[2] = {
        g_Ah + (size_t)mt * 128 * HD,
        g_Bh + (size_t)nt * 128 * HD
    };
    #pragma unroll
    for (int arr = 0; arr < 2; arr++) {
        #pragma unroll
        for (int it = 0; it < 8; it++) {
            int i  = tid + it * 128;
            int r  = i >> 3;
            int g  = i & 7;
            const void* src = srcs[arr] + (size_t)r * HD + c * LBK + g * 8;
            uint32_t dst = smbase + (uint32_t)(s * STAGE_ELEMS + arr * ARR_ELEMS) * 2u
                         + (uint32_t)(r * (LDT * 2) + g * 16);
            cp16(dst, src);
        }
    }
    asm volatile("cp.async.commit_group;" ::: "memory");
}

__global__ void __launch_bounds__(128, 2) logits_wmma(const float* __restrict__ b_out,
                                                      float* __restrict__ out)
{
    extern __shared__ __align__(16) char dynsmem[];
    __half* sm = (__half*)dynsmem;
    const uint32_t smbase = smem_u32(dynsmem);

    const int tid = threadIdx.x;
    const int wid = tid >> 5, lane = tid & 31;
    const int nt = blockIdx.x;
    const int mt = blockIdx.y;
    const int warp_m = wid >> 1;
    const int warp_n = wid & 1;

    wmma::fragment<wmma::accumulator, 16, 16, 16, float> acc[4][4];
    #pragma unroll
    for (int i = 0; i < 4; i++)
        #pragma unroll
        for (int j = 0; j < 4; j++)
            wmma::fill_fragment(acc[i][j], 0.f);

    load_stage_logits(tid, mt, nt, 0, smbase, 0);
    load_stage_logits(tid, mt, nt, 1, smbase, 1);

    for (int c = 0; c < 8; c++) {
        const int s = c & 1;
        if (c < 7) asm volatile("cp.async.wait_group 1;" ::: "memory");
        else       asm volatile("cp.async.wait_group 0;" ::: "memory");
        __syncthreads();

        const __half* As = sm + s * STAGE_ELEMS;
        const __half* Bs = As + ARR_ELEMS;

        #pragma unroll
        for (int kk = 0; kk < LBK; kk += 16) {
            wmma::fragment<wmma::matrix_a, 16, 16, 16, __half, wmma::row_major> a[4];
            wmma::fragment<wmma::matrix_b, 16, 16, 16, __half, wmma::col_major> b[4];
            #pragma unroll
            for (int i = 0; i < 4; i++)
                wmma::load_matrix_sync(a[i], As + (warp_m * 64 + i * 16) * LDT + kk, LDT);
            #pragma unroll
            for (int j = 0; j < 4; j++)
                wmma::load_matrix_sync(b[j], Bs + (warp_n * 64 + j * 16) * LDT + kk, LDT);
            #pragma unroll
            for (int i = 0; i < 4; i++)
                #pragma unroll
                for (int j = 0; j < 4; j++)
                    wmma::mma_sync(acc[i][j], a[i], b[j], acc[i][j]);
        }
        __syncthreads();

        if (c + 2 < 8) load_stage_logits(tid, mt, nt, c + 2, smbase, s);
    }

    __syncthreads();
    float* ws = (float*)dynsmem + wid * 64 * LDC_W;
    #pragma unroll
    for (int i = 0; i < 4; i++)
        #pragma unroll
        for (int j = 0; j < 4; j++)
            wmma::store_matrix_sync(ws + i * 16 * LDC_W + j * 16, acc[i][j],
                                    LDC_W, wmma::mem_row_major);
    __syncwarp();

    const int row0 = mt * 128 + warp_m * 64;
    const int n0   = nt * 128 + warp_n * 64;
    #pragma unroll
    for (int it = 0; it < 32; it++) {
        int idx = lane + it * 32;
        int r   = idx >> 4;
        int c4  = (idx & 15) * 4;
        float4 v = *(float4*)(ws + r * LDC_W + c4);
        v.x += b_out[n0 + c4 + 0];
        v.y += b_out[n0 + c4 + 1];
        v.z += b_out[n0 + c4 + 2];
        v.w += b_out[n0 + c4 + 3];
        *(float4*)(out + (size_t)(row0 + r) * VV + n0 + c4) = v;
    }
}

// ---------------- launch ----------------
extern "C" void kernel_launch(void* const* d_in, const int* in_sizes, int n_in,
                              void* d_out, int out_size)
{
    const float* x      = (const float*)d_in[0];
    const int*   inlen  = (const int*)  d_in[1];
    const float* enc    = (const float*)d_in[2];
    const int*   enclen = (const int*)  d_in[3];
    const float* W_ih   = (const float*)d_in[4];
    const float* W_hh   = (const float*)d_in[5];
    const float* b_ih   = (const float*)d_in[6];
    const float* b_hh   = (const float*)d_in[7];
    const float* W_attn = (const float*)d_in[8];
    const float* b_attn = (const float*)d_in[9];
    const float* v_w    = (const float*)d_in[10];
    const float* W_dense= (const float*)d_in[12];
    const float* b_dense= (const float*)d_in[13];
    const float* W_out  = (const float*)d_in[14];
    const float* b_out  = (const float*)d_in[15];

    float* out = (float*)d_out;

    float* xp    = nullptr; cudaGetSymbolAddress((void**)&xp,    g_xp);
    float* encp  = nullptr; cudaGetSymbolAddress((void**)&encp,  g_encp);
    float* decp  = nullptr; cudaGetSymbolAddress((void**)&decp,  g_decp);
    float* hlast = nullptr; cudaGetSymbolAddress((void**)&hlast, g_hlast);
    __half* Ah   = nullptr; cudaGetSymbolAddress((void**)&Ah,   g_Ah);
    __half* ench = nullptr; cudaGetSymbolAddress((void**)&ench, g_ench);
    __half* cat  = nullptr; cudaGetSymbolAddress((void**)&cat,  g_cat);
    __half* Wae  = nullptr; cudaGetSymbolAddress((void**)&Wae,  g_Wae);
    __half* Wad  = nullptr; cudaGetSymbolAddress((void**)&Wad,  g_Wad);
    __half* Wdh  = nullptr; cudaGetSymbolAddress((void**)&Wdh,  g_Wdh);
    __half* xh   = nullptr; cudaGetSymbolAddress((void**)&xh,   g_xh);
    __half* Wih  = nullptr; cudaGetSymbolAddress((void**)&Wih,  g_Wih);

    cudaFuncSetAttribute(logits_wmma, cudaFuncAttributeMaxDynamicSharedMemorySize, SMEM_LOGITS);

    // #1: merged convert (x, W_ih)
    convA<<<(NA1 + NA2) / 2048, 256>>>(x, W_ih);

    // #2: x_proj
    hgemm_nt<<<dim3(G3 / 64, (BB * TD) / 64), 128, HSMEM>>>(xh, HD, Wih, HD, b_ih, xp, G3, HD, 0);

    // #3: W_out convert (independent)
    convWout<<<((size_t)VV * HD) / 2048, 256>>>(W_out);

    // #4: GRU scan  <-- profiled launch position
    gru_scan<<<96, 256>>>(W_hh, b_hh, inlen);

    // #5: merged convert (W_dense, W_attn, enc)
    convB<<<(NB1 + NB2 + NB3) / 2048, 256>>>(W_dense, W_attn, enc);

    // #6,7: attention projections
    hgemm_nt<<<dim3(HD / 64, (BB * TE) / 64), 128, HSMEM>>>(ench, HD, Wae, HD, nullptr, encp, HD, HD, 0);
    hgemm_nt<<<dim3(HD / 64, (BB * TD) / 64), 128, HSMEM>>>(cat, 2 * HD, Wad, HD, nullptr, decp, HD, HD, 0);

    // #8: attention
    attn_kernel<<<BB * TD, 256>>>(encp, decp, enc, inlen, enclen, b_attn, v_w, cat);

    // #9: dense
    hgemm_nt<<<dim3(HD / 64, (BB * TD) / 64), 128, HSMEM>>>(cat, 2 * HD, Wdh, 2 * HD, b_dense, Ah, HD,
                                                            2 * HD, HF_TANH | HF_OUTH);

    // #10: logits
    logits_wmma<<<dim3(VV / 128, (BB * TD) / 128), 128, SMEM_LOGITS>>>(b_out, out);

    // h_last tail via async D2D copy
    cudaMemcpyAsync(out + LOGITS_ELEMS, hlast, BB * HD * sizeof(float),
                    cudaMemcpyDeviceToDevice);
}

// round 16
// speedup vs baseline: 1.7662x; 1.4680x over previous
#include <cuda_runtime.h>
#include <cuda_fp16.h>
#include <mma.h>
#include <math.h>
#include <stdint.h>
#include <cooperative_groups.h>

using namespace nvcuda;
namespace cg = cooperative_groups;

// Problem constants
#define BB   16
#define TD   64
#define TE   64
#define HD   512
#define G3   1536
#define VV   32000
#define LOGITS_ELEMS (BB*TD*VV)   // 32768000

// ---------------- scratch (__device__ globals, no allocation) ----------------
__device__ float g_xp   [BB*TD*G3];
__device__ float g_encp [BB*TE*HD];
__device__ float g_decp [BB*TD*HD];
__device__ float g_hlast[BB*HD];

// fp16 operands
__device__ __half g_Ah  [BB*TD*HD];
__device__ __half g_Bh  [(size_t)VV*HD];
__device__ __half g_ench[BB*TE*HD];
__device__ __half g_cat [BB*TD*2*HD];
__device__ __half g_Wae [HD*HD];
__device__ __half g_Wad [HD*HD];
__device__ __half g_Wdh [HD*2*HD];
__device__ __half g_xh  [BB*TD*HD];
__device__ __half g_Wih [G3*HD];

// ---------------- helpers ----------------
__device__ __forceinline__ uint32_t smem_u32(const void* p) {
    uint32_t a;
    asm("{ .reg .u64 t; cvta.to.shared.u64 t, %1; cvt.u32.u64 %0, t; }" : "=r"(a) : "l"(p));
    return a;
}
__device__ __forceinline__ void cp16(uint32_t s, const void* g) {
    asm volatile("cp.async.cg.shared.global [%0], [%1], 16;" :: "r"(s), "l"(g));
}
__device__ __forceinline__ void cvt8(const float* sp, __half* dp) {
    float4 v0 = *(const float4*)sp;
    float4 v1 = *(const float4*)(sp + 4);
    __half2* d = (__half2*)dp;
    d[0] = __floats2half2_rn(v0.x, v0.y);
    d[1] = __floats2half2_rn(v0.z, v0.w);
    d[2] = __floats2half2_rn(v1.x, v1.y);
    d[3] = __floats2half2_rn(v1.z, v1.w);
}
__device__ __forceinline__ float fast_sigmoid(float a) {
    return __fdividef(1.f, 1.f + __expf(-a));
}
__device__ __forceinline__ float fast_tanh_acc(float a) {
    float t = __expf(-2.f * a);
    return __fdividef(2.f, 1.f + t) - 1.f;
}
__device__ __forceinline__ float tanh_fast(float x) {
    float y;
    asm("tanh.approx.f32 %0, %1;" : "=f"(y) : "f"(x));
    return y;
}

// ---------------- merged convert A: x -> xh, W_ih -> Wih ----------------
#define NA1 (BB*TD*HD)
#define NA2 (G3*HD)
__global__ void convA(const float* __restrict__ x, const float* __restrict__ Wih)
{
    int i = (blockIdx.x * 256 + threadIdx.x) * 8;
    if (i < NA1) {
        cvt8(x + i, g_xh + i);
    } else {
        int j = i - NA1;
        if (j < NA2) cvt8(Wih + j, g_Wih + j);
    }
}

// ---------------- merged convert B ----------------
#define NB1 (HD*2*HD)
#define NB2 (HD*2*HD)
#define NB3 (BB*TE*HD)
__global__ void convB(const float* __restrict__ Wdense,
                      const float* __restrict__ Wattn,
                      const float* __restrict__ enc)
{
    int i = (blockIdx.x * 256 + threadIdx.x) * 8;
    if (i < NB1) {
        cvt8(Wdense + i, g_Wdh + i);
    } else if (i < NB1 + NB2) {
        int j = i - NB1;
        int row = j >> 10, col = j & 1023;
        __half* dst = (col < HD) ? (g_Wae + row * HD + col)
                                 : (g_Wad + row * HD + (col - HD));
        cvt8(Wattn + j, dst);
    } else {
        int j = i - NB1 - NB2;
        if (j < NB3) cvt8(enc + j, g_ench + j);
    }
}

__global__ void convWout(const float* __restrict__ W_out)
{
    int i = (blockIdx.x * 256 + threadIdx.x) * 8;
    cvt8(W_out + i, g_Bh + i);
}

// ---------------- cluster GRU scan ----------------
// 8 clusters x 8 CTAs. Cluster c owns batches {2c, 2c+1}.
// CTA rank r holds fp16 W_hh rows [r*192,(r+1)*192) in SMEM (padded uint4 rows).
// Step: phase1 matvec -> spre (threads 192-255 prefetch x_proj) | cluster.sync |
//       phase2 gates for j in [r*64,(r+1)*64) x 2 batches, DSMEM pre reads,
//       h broadcast via 8 remote SMEM stores | cluster.sync.
#define RPC   192                 // W rows per CTA
#define WPAD  65                  // uint4 per row (64 + 1 pad -> conflict-free)
#define SMEM_W    (RPC * WPAD * 16)        // 199680
#define OFF_SH    SMEM_W                   // float sh[2*512]   (4096)
#define OFF_SPRE  (OFF_SH + 4096)          // float spre[2*192] (1536)
#define OFF_SPX   (OFF_SPRE + 1536)        // float spx[2*1536] (12288)
#define SMEM_GRU  (OFF_SPX + 12288)        // 217600

__global__ void __cluster_dims__(8, 1, 1) __launch_bounds__(256, 1)
gru_scan(const float* __restrict__ W_hh,
         const float* __restrict__ b_hh,
         const int*   __restrict__ lengths)
{
    extern __shared__ __align__(16) char dsm[];
    uint4* sWv  = (uint4*)dsm;
    float* sh   = (float*)(dsm + OFF_SH);     // [bat*512 + j]
    float* spre = (float*)(dsm + OFF_SPRE);   // [bat*192 + local_row]
    float* spx  = (float*)(dsm + OFF_SPX);    // [bat*1536 + g]

    cg::cluster_group cluster = cg::this_cluster();
    const int rank = (int)cluster.block_rank();     // 0..7
    const int cid  = blockIdx.x >> 3;               // 0..7
    const int b0 = cid * 2, b1 = cid * 2 + 1;
    const int tid = threadIdx.x;

    // load my W_hh slice as fp16 (rows rank*192 .. +192)
    const int grow0 = rank * RPC;
    for (int idx = tid; idx < RPC * 64; idx += 256) {
        int row = idx >> 6, g = idx & 63;
        const float* src = W_hh + (size_t)(grow0 + row) * HD + g * 8;
        float4 a = *(const float4*)src;
        float4 b = *(const float4*)(src + 4);
        __half2 p0 = __floats2half2_rn(a.x, a.y);
        __half2 p1 = __floats2half2_rn(a.z, a.w);
        __half2 p2 = __floats2half2_rn(b.x, b.y);
        __half2 p3 = __floats2half2_rn(b.z, b.w);
        uint4 v;
        v.x = *reinterpret_cast<uint32_t*>(&p0);
        v.y = *reinterpret_cast<uint32_t*>(&p1);
        v.z = *reinterpret_cast<uint32_t*>(&p2);
        v.w = *reinterpret_cast<uint32_t*>(&p3);
        sWv[row * WPAD + g] = v;
    }
    for (int i = tid; i < 1024; i += 256) sh[i] = 0.f;
    const int len0 = lengths[b0], len1 = lengths[b1];
    __syncthreads();

    const int jl  = tid & 63;
    const int bat = tid >> 6;            // for tid<128
    const int j   = rank * 64 + jl;
    // pre-activation source rows & owners (constant over t)
    const int gr = j, gz = 512 + j, gn = 1024 + j;
    const int owr = gr / RPC, lor = gr % RPC;
    const int owz = gz / RPC, loz = gz % RPC;
    const int own = gn / RPC, lon = gn % RPC;

    for (int t = 0; t < TD; t++) {
        // ---- phase 1 ----
        if (tid < RPC) {
            const uint4* wrow = sWv + tid * WPAD;
            const float* sh0 = sh;
            const float* sh1 = sh + 512;
            float a0 = 0.f, a1 = 0.f;
            #pragma unroll 8
            for (int g = 0; g < 64; g++) {
                uint4 w = wrow[g];
                __half2 w0 = *reinterpret_cast<__half2*>(&w.x);
                __half2 w1 = *reinterpret_cast<__half2*>(&w.y);
                __half2 w2 = *reinterpret_cast<__half2*>(&w.z);
                __half2 w3 = *reinterpret_cast<__half2*>(&w.w);
                float2 f0 = __half22float2(w0), f1 = __half22float2(w1);
                float2 f2 = __half22float2(w2), f3 = __half22float2(w3);
                float4 hA = *(const float4*)(sh0 + g * 8);
                float4 hB = *(const float4*)(sh0 + g * 8 + 4);
                a0 += f0.x * hA.x + f0.y * hA.y + f1.x * hA.z + f1.y * hA.w
                    + f2.x * hB.x + f2.y * hB.y + f3.x * hB.z + f3.y * hB.w;
                float4 gA = *(const float4*)(sh1 + g * 8);
                float4 gB = *(const float4*)(sh1 + g * 8 + 4);
                a1 += f0.x * gA.x + f0.y * gA.y + f1.x * gA.z + f1.y * gA.w
                    + f2.x * gB.x + f2.y * gB.y + f3.x * gB.z + f3.y * gB.w;
            }
            spre[tid]       = a0;
            spre[RPC + tid] = a1;
        } else {
            // threads 192-255 prefetch this step's x_proj rows for both batches
            int i2 = tid - RPC;   // 0..63
            const float4* x0 = (const float4*)(g_xp + ((size_t)b0 * TD + t) * G3);
            const float4* x1 = (const float4*)(g_xp + ((size_t)b1 * TD + t) * G3);
            float4* d0 = (float4*)spx;
            float4* d1 = (float4*)(spx + G3);
            #pragma unroll
            for (int q = 0; q < 6; q++) {
                d0[i2 + q * 64] = x0[i2 + q * 64];
                d1[i2 + q * 64] = x1[i2 + q * 64];
            }
        }
        cluster.sync();

        // ---- phase 2: gates for my 64-j slice x 2 batches ----
        if (tid < 128) {
            const float* rpr = (const float*)cluster.map_shared_rank(spre, owr);
            const float* rpz = (const float*)cluster.map_shared_rank(spre, owz);
            const float* rpn = (const float*)cluster.map_shared_rank(spre, own);
            float pr = rpr[bat * RPC + lor] + b_hh[gr];
            float pz = rpz[bat * RPC + loz] + b_hh[gz];
            float pn = rpn[bat * RPC + lon] + b_hh[gn];
            const float* xr = spx + bat * G3;
            float r = fast_sigmoid(xr[j] + pr);
            float z = fast_sigmoid(xr[512 + j] + pz);
            float n = fast_tanh_acc(xr[1024 + j] + r * pn);
            float hold = sh[bat * 512 + j];
            float hnew = (1.f - z) * n + z * hold;
            const int bb  = bat ? b1 : b0;
            const int len = bat ? len1 : len0;
            bool valid = (t < len);
            float hkeep = valid ? hnew : hold;
            #pragma unroll
            for (int dst = 0; dst < 8; dst++) {
                float* hp = (float*)cluster.map_shared_rank(sh, dst);
                hp[bat * 512 + j] = hkeep;
            }
            g_cat[((size_t)bb * TD + t) * (2 * HD) + j] = __float2half(valid ? hnew : 0.f);
            if (t == TD - 1) g_hlast[(size_t)bb * HD + j] = hkeep;
        }
        cluster.sync();
    }
}

// ---------------- attention (unchanged from r15) ----------------
__global__ void attn_kernel(const float* __restrict__ encp,
                            const float* __restrict__ decp,
                            const float* __restrict__ enc,
                            const int*   __restrict__ dlen,
                            const int*   __restrict__ elen,
                            const float* __restrict__ b_attn,
                            const float* __restrict__ v_w,
                            __half* __restrict__ cat)
{
    const int bd = blockIdx.x;
    const int b  = bd >> 6;
    const int d  = bd & 63;
    const int tid = threadIdx.x;

    __shared__ float s_dp[HD];
    __shared__ float s_vw[HD];
    __shared__ float s_en[TE];
    __shared__ float s_mx, s_ssum;

    __half* ctx_out = cat + (size_t)bd * (2 * HD) + HD;
    const int Dl = dlen[b];
    const int El = elen[b];

    if (d >= Dl) {
        for (int i = tid; i < HD; i += 256) ctx_out[i] = __float2half(0.f);
        return;
    }

    for (int i = tid; i < HD; i += 256) {
        s_dp[i] = decp[(size_t)bd * HD + i] + b_attn[i];
        s_vw[i] = v_w[i];
    }
    __syncthreads();

    const int warp = tid >> 5, lane = tid & 31;
    for (int e = warp; e < El; e += 8) {
        const float* ep = encp + ((size_t)b * TE + e) * HD;
        float sum = 0.f;
        #pragma unroll 4
        for (int h = lane; h < HD; h += 32)
            sum += tanh_fast(ep[h] + s_dp[h]) * s_vw[h];
        #pragma unroll
        for (int off = 16; off; off >>= 1)
            sum += __shfl_xor_sync(0xffffffffu, sum, off);
        if (lane == 0) s_en[e] = sum;
    }
    __syncthreads();

    if (tid < 32) {
        float mx = -1e30f;
        for (int e = lane; e < El; e += 32) mx = fmaxf(mx, s_en[e]);
        #pragma unroll
        for (int off = 16; off; off >>= 1)
            mx = fmaxf(mx, __shfl_xor_sync(0xffffffffu, mx, off));
        float ss = 0.f;
        for (int e = lane; e < El; e += 32) ss += __expf(s_en[e] - mx);
        #pragma unroll
        for (int off = 16; off; off >>= 1)
            ss += __shfl_xor_sync(0xffffffffu, ss, off);
        if (lane == 0) { s_mx = mx; s_ssum = ss; }
    }
    __syncthreads();
    if (tid < TE) s_en[tid] = (tid < El) ? __fdividef(__expf(s_en[tid] - s_mx), s_ssum) : 0.f;
    __syncthreads();

    for (int h = tid; h < HD; h += 256) {
        float a = 0.f;
        for (int e = 0; e < El; e++)
            a += s_en[e] * enc[((size_t)b * TE + e) * HD + h];
        ctx_out[h] = __float2half(a);
    }
}

// ---------------- generic fp16 wmma NT GEMM (unchanged) ----------------
#define HF_TANH 1
#define HF_OUTH 2
#define HLDT 72
#define HARR (64 * HLDT)
#define HSTAGE (2 * HARR)
#define HSMEM (2 * HSTAGE * 2)
#define HLDC 36

__device__ __forceinline__ void hload_stage(const __half* __restrict__ A, int lda,
                                            const __half* __restrict__ B, int ldb,
                                            int row0, int n0, int c,
                                            uint32_t smbase, int s, int tid)
{
    #pragma unroll
    for (int it = 0; it < 4; it++) {
        int i = tid + it * 128;
        int r = i >> 3, c4 = i & 7;
        const void* src = A + (size_t)(row0 + r) * lda + c * 64 + c4 * 8;
        cp16(smbase + (uint32_t)(s * HSTAGE) * 2u + (uint32_t)(r * (HLDT * 2) + c4 * 16), src);
    }
    #pragma unroll
    for (int it = 0; it < 4; it++) {
        int i = tid + it * 128;
        int r = i >> 3, c4 = i & 7;
        const void* src = B + (size_t)(n0 + r) * ldb + c * 64 + c4 * 8;
        cp16(smbase + (uint32_t)(s * HSTAGE + HARR) * 2u + (uint32_t)(r * (HLDT * 2) + c4 * 16), src);
    }
    asm volatile("cp.async.commit_group;" ::: "memory");
}

__global__ void __launch_bounds__(128, 2) hgemm_nt(
    const __half* __restrict__ A, int lda,
    const __half* __restrict__ B, int ldb,
    const float* __restrict__ bias,
    void* __restrict__ Cout, int ldc,
    int K, int flags)
{
    extern __shared__ __align__(16) char dsm[];
    __half* sm = (__half*)dsm;
    const uint32_t smbase = smem_u32(dsm);

    const int tid = threadIdx.x;
    const int wid = tid >> 5, lane = tid & 31;
    const int brow0 = blockIdx.y * 64;
    const int bn0   = blockIdx.x * 64;
    const int warp_m = wid >> 1, warp_n = wid & 1;
    const int nch = K / 64;

    wmma::fragment<wmma::accumulator, 16, 16, 16, float> acc[2][2];
    #pragma unroll
    for (int i = 0; i < 2; i++)
        #pragma unroll
        for (int j = 0; j < 2; j++)
            wmma::fill_fragment(acc[i][j], 0.f);

    hload_stage(A, lda, B, ldb, brow0, bn0, 0, smbase, 0, tid);
    hload_stage(A, lda, B, ldb, brow0, bn0, 1, smbase, 1, tid);

    for (int c = 0; c < nch; c++) {
        const int s = c & 1;
        if (c < nch - 1) asm volatile("cp.async.wait_group 1;" ::: "memory");
        else             asm volatile("cp.async.wait_group 0;" ::: "memory");
        __syncthreads();

        const __half* As = sm + s * HSTAGE;
        const __half* Bs = As + HARR;

        #pragma unroll
        for (int kk = 0; kk < 64; kk += 16) {
            wmma::fragment<wmma::matrix_a, 16, 16, 16, __half, wmma::row_major> a[2];
            wmma::fragment<wmma::matrix_b, 16, 16, 16, __half, wmma::col_major> b[2];
            #pragma unroll
            for (int i = 0; i < 2; i++)
                wmma::load_matrix_sync(a[i], As + (warp_m * 32 + i * 16) * HLDT + kk, HLDT);
            #pragma unroll
            for (int j = 0; j < 2; j++)
                wmma::load_matrix_sync(b[j], Bs + (warp_n * 32 + j * 16) * HLDT + kk, HLDT);
            #pragma unroll
            for (int i = 0; i < 2; i++)
                #pragma unroll
                for (int j = 0; j < 2; j++)
                    wmma::mma_sync(acc[i][j], a[i], b[j], acc[i][j]);
        }
        __syncthreads();

        if (c + 2 < nch) hload_stage(A, lda, B, ldb, brow0, bn0, c + 2, smbase, s, tid);
    }

    __syncthreads();
    float* ws = (float*)dsm + wid * 32 * HLDC;
    #pragma unroll
    for (int i = 0; i < 2; i++)
        #pragma unroll
        for (int j = 0; j < 2; j++)
            wmma::store_matrix_sync(ws + i * 16 * HLDC + j * 16, acc[i][j],
                                    HLDC, wmma::mem_row_major);
    __syncwarp();

    const int row0 = brow0 + warp_m * 32;
    const int n0   = bn0 + warp_n * 32;
    #pragma unroll
    for (int it = 0; it < 8; it++) {
        int idx = lane + it * 32;
        int r   = idx >> 3;
        int c4  = (idx & 7) * 4;
        float4 v = *(float4*)(ws + r * HLDC + c4);
        if (bias) {
            v.x += bias[n0 + c4 + 0];
            v.y += bias[n0 + c4 + 1];
            v.z += bias[n0 + c4 + 2];
            v.w += bias[n0 + c4 + 3];
        }
        if (flags & HF_TANH) {
            v.x = fast_tanh_acc(v.x); v.y = fast_tanh_acc(v.y);
            v.z = fast_tanh_acc(v.z); v.w = fast_tanh_acc(v.w);
        }
        if (flags & HF_OUTH) {
            __half* cp = (__half*)Cout + (size_t)(row0 + r) * ldc + n0 + c4;
            *(__half2*)(cp)     = __floats2half2_rn(v.x, v.y);
            *(__half2*)(cp + 2) = __floats2half2_rn(v.z, v.w);
        } else {
            *(float4*)((float*)Cout + (size_t)(row0 + r) * ldc + n0 + c4) = v;
        }
    }
}

// ---------------- wmma logits GEMM (unchanged) ----------------
#define LBK   64
#define LDT   72
#define ARR_ELEMS (128 * LDT)
#define STAGE_ELEMS (2 * ARR_ELEMS)
#define LDC_W 68
#define SMEM_LOGITS 73728

__device__ __forceinline__ void load_stage_logits(int tid, int mt, int nt, int c,
                                                  uint32_t smbase, int s)
{
    const __half* srcs[2] = {
        g_Ah + (size_t)mt * 128 * HD,
        g_Bh + (size_t)nt * 128 * HD
    };
    #pragma unroll
    for (int arr = 0; arr < 2; arr++) {
        #pragma unroll
        for (int it = 0; it < 8; it++) {
            int i  = tid + it * 128;
            int r  = i >> 3;
            int g  = i & 7;
            const void* src = srcs[arr] + (size_t)r * HD + c * LBK + g * 8;
            uint32_t dst = smbase + (uint32_t)(s * STAGE_ELEMS + arr * ARR_ELEMS) * 2u
                         + (uint32_t)(r * (LDT * 2) + g * 16);
            cp16(dst, src);
        }
    }
    asm volatile("cp.async.commit_group;" ::: "memory");
}

__global__ void __launch_bounds__(128, 2) logits_wmma(const float* __restrict__ b_out,
                                                      float* __restrict__ out)
{
    extern __shared__ __align__(16) char dynsmem[];
    __half* sm = (__half*)dynsmem;
    const uint32_t smbase = smem_u32(dynsmem);

    const int tid = threadIdx.x;
    const int wid = tid >> 5, lane = tid & 31;
    const int nt = blockIdx.x;
    const int mt = blockIdx.y;
    const int warp_m = wid >> 1;
    const int warp_n = wid & 1;

    wmma::fragment<wmma::accumulator, 16, 16, 16, float> acc[4][4];
    #pragma unroll
    for (int i = 0; i < 4; i++)
        #pragma unroll
        for (int j = 0; j < 4; j++)
            wmma::fill_fragment(acc[i][j], 0.f);

    load_stage_logits(tid, mt, nt, 0, smbase, 0);
    load_stage_logits(tid, mt, nt, 1, smbase, 1);

    for (int c = 0; c < 8; c++) {
        const int s = c & 1;
        if (c < 7) asm volatile("cp.async.wait_group 1;" ::: "memory");
        else       asm volatile("cp.async.wait_group 0;" ::: "memory");
        __syncthreads();

        const __half* As = sm + s * STAGE_ELEMS;
        const __half* Bs = As + ARR_ELEMS;

        #pragma unroll
        for (int kk = 0; kk < LBK; kk += 16) {
            wmma::fragment<wmma::matrix_a, 16, 16, 16, __half, wmma::row_major> a[4];
            wmma::fragment<wmma::matrix_b, 16, 16, 16, __half, wmma::col_major> b[4];
            #pragma unroll
            for (int i = 0; i < 4; i++)
                wmma::load_matrix_sync(a[i], As + (warp_m * 64 + i * 16) * LDT + kk, LDT);
            #pragma unroll
            for (int j = 0; j < 4; j++)
                wmma::load_matrix_sync(b[j], Bs + (warp_n * 64 + j * 16) * LDT + kk, LDT);
            #pragma unroll
            for (int i = 0; i < 4; i++)
                #pragma unroll
                for (int j = 0; j < 4; j++)
                    wmma::mma_sync(acc[i][j], a[i], b[j], acc[i][j]);
        }
        __syncthreads();

        if (c + 2 < 8) load_stage_logits(tid, mt, nt, c + 2, smbase, s);
    }

    __syncthreads();
    float* ws = (float*)dynsmem + wid * 64 * LDC_W;
    #pragma unroll
    for (int i = 0; i < 4; i++)
        #pragma unroll
        for (int j = 0; j < 4; j++)
            wmma::store_matrix_sync(ws + i * 16 * LDC_W + j * 16, acc[i][j],
                                    LDC_W, wmma::mem_row_major);
    __syncwarp();

    const int row0 = mt * 128 + warp_m * 64;
    const int n0   = nt * 128 + warp_n * 64;
    #pragma unroll
    for (int it = 0; it < 32; it++) {
        int idx = lane + it * 32;
        int r   = idx >> 4;
        int c4  = (idx & 15) * 4;
        float4 v = *(float4*)(ws + r * LDC_W + c4);
        v.x += b_out[n0 + c4 + 0];
        v.y += b_out[n0 + c4 + 1];
        v.z += b_out[n0 + c4 + 2];
        v.w += b_out[n0 + c4 + 3];
        *(float4*)(out + (size_t)(row0 + r) * VV + n0 + c4) = v;
    }
}

// ---------------- launch ----------------
extern "C" void kernel_launch(void* const* d_in, const int* in_sizes, int n_in,
                              void* d_out, int out_size)
{
    const float* x      = (const float*)d_in[0];
    const int*   inlen  = (const int*)  d_in[1];
    const float* enc    = (const float*)d_in[2];
    const int*   enclen = (const int*)  d_in[3];
    const float* W_ih   = (const float*)d_in[4];
    const float* W_hh   = (const float*)d_in[5];
    const float* b_ih   = (const float*)d_in[6];
    const float* b_hh   = (const float*)d_in[7];
    const float* W_attn = (const float*)d_in[8];
    const float* b_attn = (const float*)d_in[9];
    const float* v_w    = (const float*)d_in[10];
    const float* W_dense= (const float*)d_in[12];
    const float* b_dense= (const float*)d_in[13];
    const float* W_out  = (const float*)d_in[14];
    const float* b_out  = (const float*)d_in[15];

    float* out = (float*)d_out;

    float* xp    = nullptr; cudaGetSymbolAddress((void**)&xp,    g_xp);
    float* encp  = nullptr; cudaGetSymbolAddress((void**)&encp,  g_encp);
    float* decp  = nullptr; cudaGetSymbolAddress((void**)&decp,  g_decp);
    float* hlast = nullptr; cudaGetSymbolAddress((void**)&hlast, g_hlast);
    __half* Ah   = nullptr; cudaGetSymbolAddress((void**)&Ah,   g_Ah);
    __half* ench = nullptr; cudaGetSymbolAddress((void**)&ench, g_ench);
    __half* cat  = nullptr; cudaGetSymbolAddress((void**)&cat,  g_cat);
    __half* Wae  = nullptr; cudaGetSymbolAddress((void**)&Wae,  g_Wae);
    __half* Wad  = nullptr; cudaGetSymbolAddress((void**)&Wad,  g_Wad);
    __half* Wdh  = nullptr; cudaGetSymbolAddress((void**)&Wdh,  g_Wdh);
    __half* xh   = nullptr; cudaGetSymbolAddress((void**)&xh,   g_xh);
    __half* Wih  = nullptr; cudaGetSymbolAddress((void**)&Wih,  g_Wih);

    cudaFuncSetAttribute(logits_wmma, cudaFuncAttributeMaxDynamicSharedMemorySize, SMEM_LOGITS);
    cudaFuncSetAttribute(gru_scan,    cudaFuncAttributeMaxDynamicSharedMemorySize, SMEM_GRU);

    // #1: merged convert (x, W_ih)
    convA<<<(NA1 + NA2) / 2048, 256>>>(x, W_ih);

    // #2: x_proj
    hgemm_nt<<<dim3(G3 / 64, (BB * TD) / 64), 128, HSMEM>>>(xh, HD, Wih, HD, b_ih, xp, G3, HD, 0);

    // #3: W_out convert
    convWout<<<((size_t)VV * HD) / 2048, 256>>>(W_out);

    // #4: cluster GRU scan  <-- profiled launch position
    gru_scan<<<64, 256, SMEM_GRU>>>(W_hh, b_hh, inlen);

    // #5: merged convert (W_dense, W_attn, enc)
    convB<<<(NB1 + NB2 + NB3) / 2048, 256>>>(W_dense, W_attn, enc);

    // #6,7: attention projections
    hgemm_nt<<<dim3(HD / 64, (BB * TE) / 64), 128, HSMEM>>>(ench, HD, Wae, HD, nullptr, encp, HD, HD, 0);
    hgemm_nt<<<dim3(HD / 64, (BB * TD) / 64), 128, HSMEM>>>(cat, 2 * HD, Wad, HD, nullptr, decp, HD, HD, 0);

    // #8: attention
    attn_kernel<<<BB * TD, 256>>>(encp, decp, enc, inlen, enclen, b_attn, v_w, cat);

    // #9: dense
    hgemm_nt<<<dim3(HD / 64, (BB * TD) / 64), 128, HSMEM>>>(cat, 2 * HD, Wdh, 2 * HD, b_dense, Ah, HD,
                                                            2 * HD, HF_TANH | HF_OUTH);

    // #10: logits
    logits_wmma<<<dim3(VV / 128, (BB * TD) / 128), 128, SMEM_LOGITS>>>(b_out, out);

    // h_last tail via async D2D copy
    cudaMemcpyAsync(out + LOGITS_ELEMS, hlast, BB * HD * sizeof(float),
                    cudaMemcpyDeviceToDevice);
}